// round 11
// baseline (speedup 1.0000x reference)
#include <cuda_runtime.h>
#include <math.h>
#include <stdint.h>

#define F   128
#define S   10
#define KC  16
#define MAXN 200000
#define MAXB 20000

typedef unsigned long long ull;

// static scratch (allocation-free rule)
__device__ float    g_pre[(size_t)MAXN * F];  // t_j * (q_j @ mask)
__device__ float    g_ln[MAXN];               // t_j . a_neigh
__device__ uint32_t g_wB[32 * 8 * 32 * 4];    // weight tf32 B-frags (out GEMM)
__device__ uint32_t g_cB[16 * 32 * 4];        // center tf32 B-frags (cross)
__device__ uint32_t g_mB[16 * 32 * 4];        // mask tf32 B-frags (maskMM)
__device__ float    g_c2[16];                 // |center_k|^2

// ---- packed f32x2 helpers ----
__device__ __forceinline__ ull ffma2(ull a, ull b, ull c) {
    ull d; asm("fma.rn.f32x2 %0,%1,%2,%3;" : "=l"(d) : "l"(a), "l"(b), "l"(c)); return d;
}
__device__ __forceinline__ float2 funpack(ull a) {
    float2 f; asm("mov.b64 {%0,%1},%2;" : "=f"(f.x), "=f"(f.y) : "l"(a)); return f;
}
__device__ __forceinline__ float fsum2(ull a) { float2 f = funpack(a); return f.x + f.y; }

__device__ __forceinline__ uint32_t tf32cvt(float x) {
    uint32_t u; asm("cvt.rna.tf32.f32 %0,%1;" : "=r"(u) : "f"(x)); return u;
}
__device__ __forceinline__ void mma_tf32(float* d, const uint32_t* a,
                                         uint32_t b0, uint32_t b1) {
    asm("mma.sync.aligned.m16n8k8.row.col.f32.tf32.tf32.f32 "
        "{%0,%1,%2,%3},{%4,%5,%6,%7},{%8,%9},{%0,%1,%2,%3};"
        : "+f"(d[0]), "+f"(d[1]), "+f"(d[2]), "+f"(d[3])
        : "r"(a[0]), "r"(a[1]), "r"(a[2]), "r"(a[3]), "r"(b0), "r"(b1));
}

// ---------------------------------------------------------------------------
// Kernel E: encode all constants. c2 now warp-parallel (one warp per k).
// tasks: [0,32768) wB | [32768,34816) cB | [34816,36864) mB | [36864,37376) c2
// ---------------------------------------------------------------------------
__global__ void encode_consts(const float* __restrict__ weight,
                              const float* __restrict__ center,
                              const float* __restrict__ cluster_mask) {
    int idx = blockIdx.x * 256 + threadIdx.x;
    if (idx < 32768) {                      // weight B-frags (verified R6)
        int sub = idx & 3, lane = (idx >> 2) & 31;
        int ntp = (idx >> 7) & 7, kt = idx >> 10;
        int n = ntp * 16 + (sub >> 1) * 8 + (lane >> 2);
        int k = kt * 8 + (lane & 3) + (sub & 1) * 4;
        g_wB[idx] = tf32cvt(weight[n * 256 + k]);
    } else if (idx < 34816) {               // center B-frags: b = C[n][k]
        int j = idx - 32768;
        int sub = j & 3, lane = (j >> 2) & 31, kt = j >> 7;   // kt 0..15
        int n = (sub >> 1) * 8 + (lane >> 2);                 // nt = sub>>1
        int k = kt * 8 + (lane & 3) + (sub & 1) * 4;
        g_cB[j] = tf32cvt(center[n * F + k]);
    } else if (idx < 36864) {               // mask B-frags: b = mask[k][n]
        int j = idx - 34816;
        int sub = j & 3, lane = (j >> 2) & 31, nt = j >> 7;   // nt 0..15
        int n = nt * 8 + (lane >> 2);
        int k = (sub >> 1) * 8 + (lane & 3) + (sub & 1) * 4;  // kt = sub>>1
        g_mB[j] = tf32cvt(cluster_mask[k * F + n]);
    } else if (idx < 37376) {               // c2: one warp per k
        int j = idx - 36864;                // 0..511, warp-aligned
        int k = j >> 5, lane = j & 31;
        float4 c = *(const float4*)&center[k * F + lane * 4];
        float a = c.x * c.x + c.y * c.y + c.z * c.z + c.w * c.w;
        a += __shfl_xor_sync(0xffffffffu, a, 16);
        a += __shfl_xor_sync(0xffffffffu, a, 8);
        a += __shfl_xor_sync(0xffffffffu, a, 4);
        a += __shfl_xor_sync(0xffffffffu, a, 2);
        a += __shfl_xor_sync(0xffffffffu, a, 1);
        if (lane == 0) g_c2[k] = a;
    }
}

// ---------------------------------------------------------------------------
// Kernel A: precompute via tensor cores (verified R8/R10). grid=ceil(N/128).
// ---------------------------------------------------------------------------
#define PTS 132

__global__ void __launch_bounds__(256, 3)
precompute_kernel(const float* __restrict__ neigh_table,
                  const float* __restrict__ alpha,
                  int N) {
    extern __shared__ float sm[];
    float* s_T  = sm;                       // [128][PTS]
    float* s_an = sm + 128 * PTS;           // [128]
    float* s_n2 = s_an + 128;               // [128]
    float* s_c2 = s_n2 + 128;               // [16]

    const int tid = threadIdx.x;
    const int rowbase = blockIdx.x * 128;

    if (tid < 32) ((float4*)s_an)[tid] = ((const float4*)alpha)[32 + tid];  // a_neigh
    if (tid < 16) s_c2[tid] = g_c2[tid];

    #pragma unroll
    for (int it = 0; it < 16; it++) {       // coalesced tile load
        int e = it * 256 + tid;
        int r = e >> 5, c4 = e & 31;
        int grow = min(rowbase + r, N - 1);
        float4 v = *(const float4*)&neigh_table[(size_t)grow * F + c4 * 4];
        *(float4*)&s_T[r * PTS + c4 * 4] = v;
    }
    __syncthreads();

    // ---- n2 / ln (fp32): thread = (row tid>>1, half tid&1) ----
    {
        const int r = tid >> 1, h = tid & 1;
        const float* xb = &s_T[r * PTS + h * 64];
        const float* ab = &s_an[h * 64];
        ull n2 = 0ull, ln = 0ull;
        #pragma unroll 4
        for (int ch = 0; ch < 16; ch++) {
            ulonglong2 x = *(const ulonglong2*)&xb[ch * 4];
            ulonglong2 a = *(const ulonglong2*)&ab[ch * 4];
            n2 = ffma2(x.x, x.x, n2);  n2 = ffma2(x.y, x.y, n2);
            ln = ffma2(x.x, a.x, ln);  ln = ffma2(x.y, a.y, ln);
        }
        float n2f = fsum2(n2), lnf = fsum2(ln);
        n2f += __shfl_xor_sync(0xffffffffu, n2f, 1);
        lnf += __shfl_xor_sync(0xffffffffu, lnf, 1);
        if (h == 0) {
            s_n2[r] = n2f;
            g_ln[min(rowbase + r, N - 1)] = lnf;
        }
    }

    const int l = tid & 31, w = tid >> 5;
    const int r0 = w * 16 + (l >> 2);       // lane row (and r0+8)
    const int c  = l & 3;

    // ---- cross = T @ C^T via MMA: 16 kt, N=16 (2 n-tiles) ----
    float d[2][4];
    #pragma unroll
    for (int nt = 0; nt < 2; nt++)
        #pragma unroll
        for (int i = 0; i < 4; i++) d[nt][i] = 0.f;

    #pragma unroll 4
    for (int kt = 0; kt < 16; kt++) {
        uint4 bc = *(const uint4*)&g_cB[(kt * 32 + l) * 4];
        const float* ap = &s_T[r0 * PTS + kt * 8 + c];
        uint32_t a[4];
        a[0] = tf32cvt(ap[0]);
        a[1] = tf32cvt(ap[8 * PTS]);
        a[2] = tf32cvt(ap[4]);
        a[3] = tf32cvt(ap[8 * PTS + 4]);
        mma_tf32(d[0], a, bc.x, bc.y);
        mma_tf32(d[1], a, bc.z, bc.w);
    }
    __syncthreads();                        // s_n2 ready

    // ---- q epilogue in registers ----
    float qv[2][4];
    {
        const float n2A = s_n2[r0], n2B = s_n2[r0 + 8];
        #pragma unroll
        for (int nt = 0; nt < 2; nt++) {
            int k0 = nt * 8 + 2 * c;
            float c2a = s_c2[k0] + 1.f, c2b = s_c2[k0 + 1] + 1.f;
            qv[nt][0] = 1.f / (n2A - 2.f * d[nt][0] + c2a);
            qv[nt][1] = 1.f / (n2A - 2.f * d[nt][1] + c2b);
            qv[nt][2] = 1.f / (n2B - 2.f * d[nt][2] + c2a);
            qv[nt][3] = 1.f / (n2B - 2.f * d[nt][3] + c2b);
        }
    }

    // ---- intra-warp redistribution to maskMM A-frag layout (shfl) ----
    uint32_t aq[2][4];
    {
        const unsigned FULLM = 0xffffffffu;
        const int ls1 = (l & ~3) | (c >> 1);
        const int ls2 = ls1 + 2;
        const bool odd = (c & 1) != 0;
        #pragma unroll
        for (int kt = 0; kt < 2; kt++) {
            float a0 = __shfl_sync(FULLM, qv[kt][0], ls1);
            float a1 = __shfl_sync(FULLM, qv[kt][1], ls1);
            float b0 = __shfl_sync(FULLM, qv[kt][2], ls1);
            float b1 = __shfl_sync(FULLM, qv[kt][3], ls1);
            float e0 = __shfl_sync(FULLM, qv[kt][0], ls2);
            float e1 = __shfl_sync(FULLM, qv[kt][1], ls2);
            float f0 = __shfl_sync(FULLM, qv[kt][2], ls2);
            float f1 = __shfl_sync(FULLM, qv[kt][3], ls2);
            aq[kt][0] = tf32cvt(odd ? a1 : a0);
            aq[kt][1] = tf32cvt(odd ? b1 : b0);
            aq[kt][2] = tf32cvt(odd ? e1 : e0);
            aq[kt][3] = tf32cvt(odd ? f1 : f0);
        }
    }

    const int growA = min(rowbase + r0, N - 1);
    const int growB = min(rowbase + r0 + 8, N - 1);

    // ---- m = q @ mask via MMA; pre = T * m; store ----
    #pragma unroll 4
    for (int nt = 0; nt < 16; nt++) {
        uint4 bm = *(const uint4*)&g_mB[(nt * 32 + l) * 4];
        float dm[4] = {0.f, 0.f, 0.f, 0.f};
        mma_tf32(dm, aq[0], bm.x, bm.y);
        mma_tf32(dm, aq[1], bm.z, bm.w);

        int col = nt * 8 + 2 * c;
        float2 tA = *(const float2*)&s_T[r0 * PTS + col];
        float2 tB = *(const float2*)&s_T[(r0 + 8) * PTS + col];
        float2 oA, oB;
        oA.x = tA.x * dm[0];  oA.y = tA.y * dm[1];
        oB.x = tB.x * dm[2];  oB.y = tB.y * dm[3];
        *(float2*)&g_pre[(size_t)growA * F + col] = oA;
        *(float2*)&g_pre[(size_t)growB * F + col] = oB;
    }
}

#define A_SMEM ((128 * PTS + 128 + 128 + 16) * 4)

// ---------------------------------------------------------------------------
// Kernel B: fused gather + attention + TF32 MMA GEMM. grid=ceil(B/32), blk=256.
// Register-lean phase 1: self-half stored immediately; attention computed by
// one lane per row (array-free, two passes) and published via smem. Target
// 5 blocks/SM (40 warps) for latency hiding.
// ---------------------------------------------------------------------------
#define CS 268

__global__ void __launch_bounds__(256, 5)
fused_kernel(const int* __restrict__ nodes,
             const int* __restrict__ neigh_idx,
             const float* __restrict__ self_table,
             const float* __restrict__ alpha,
             float* __restrict__ out, int B) {
    extern __shared__ float smf[];
    float* s_comb  = smf;                  // [32][CS] tf32-bit floats
    float* s_alpha = smf + 32 * CS;        // [128]
    float* s_att   = s_alpha + 128;        // [32][S] normalized att
    int*   s_ji    = (int*)(s_att + 32 * S); // [32][S]

    const int tid = threadIdx.x;
    if (tid < 32) ((float4*)s_alpha)[tid] = ((const float4*)alpha)[tid];  // a_self
    __syncthreads();

    const int m0 = blockIdx.x * 32;

    // ---- phase 1: gather + attention ----
    {
        const int r = tid >> 3, g = tid & 7;
        const int row = min(m0 + r, B - 1);
        const int node = nodes[row];
        const float4* sp = (const float4*)(self_table + (size_t)node * F + g * 16);
        float lp = 0.f;
        #pragma unroll
        for (int j = 0; j < 4; j++) {
            float4 sf = sp[j];
            float4 av = *(const float4*)&s_alpha[g * 16 + j * 4];
            lp += sf.x * av.x + sf.y * av.y + sf.z * av.z + sf.w * av.w;
            float4 a;                       // self-half written now; sf dies here
            a.x = __uint_as_float(tf32cvt(sf.x));
            a.y = __uint_as_float(tf32cvt(sf.y));
            a.z = __uint_as_float(tf32cvt(sf.z));
            a.w = __uint_as_float(tf32cvt(sf.w));
            *(float4*)&s_comb[r * CS + g * 16 + j * 4] = a;
        }
        lp += __shfl_xor_sync(0xffffffffu, lp, 1);
        lp += __shfl_xor_sync(0xffffffffu, lp, 2);
        lp += __shfl_xor_sync(0xffffffffu, lp, 4);

        if (g == 0) {                       // one lane per row: attention
            const int* nip = neigh_idx + row * S;
            float asum = 0.f;
            #pragma unroll
            for (int s = 0; s < S; s++) {
                int j = nip[s];
                asum += __expf(fmaxf(lp + g_ln[j], 0.f));
            }
            const float inv = 1.f / asum;
            #pragma unroll
            for (int s = 0; s < S; s++) {   // reloads are L1-hot
                int j = nip[s];
                s_ji[r * S + s]  = j;
                s_att[r * S + s] = __expf(fmaxf(lp + g_ln[j], 0.f)) * inv;
            }
        }
        __syncwarp();

        float4 agg[4];
        #pragma unroll
        for (int j = 0; j < 4; j++) agg[j] = make_float4(0.f, 0.f, 0.f, 0.f);
        #pragma unroll
        for (int s = 0; s < S; s++) {
            const int   j  = s_ji[r * S + s];
            const float wt = s_att[r * S + s];
            const float4* pp = (const float4*)(g_pre + (size_t)j * F + g * 16);
            #pragma unroll
            for (int jj = 0; jj < 4; jj++) {
                float4 v = pp[jj];
                agg[jj].x += wt * v.x;  agg[jj].y += wt * v.y;
                agg[jj].z += wt * v.z;  agg[jj].w += wt * v.w;
            }
        }
        #pragma unroll
        for (int j = 0; j < 4; j++) {
            float4 b;
            b.x = __uint_as_float(tf32cvt(agg[j].x));
            b.y = __uint_as_float(tf32cvt(agg[j].y));
            b.z = __uint_as_float(tf32cvt(agg[j].z));
            b.w = __uint_as_float(tf32cvt(agg[j].w));
            *(float4*)&s_comb[r * CS + 128 + g * 16 + j * 4] = b;
        }
    }
    __syncthreads();

    // ---- phase 2: TF32 MMA (verified R7/R8) ----
    {
        const int lane = tid & 31, w = tid >> 5;
        float d[2][2][4];
        #pragma unroll
        for (int mt = 0; mt < 2; mt++)
            #pragma unroll
            for (int nt = 0; nt < 2; nt++)
                #pragma unroll
                for (int i = 0; i < 4; i++) d[mt][nt][i] = 0.f;

        const uint32_t* wB = &g_wB[((size_t)w * 32 + lane) * 4];
        const int arow = lane >> 2, acol = lane & 3;

        #pragma unroll 4
        for (int kt = 0; kt < 32; kt++) {
            uint4 b = *(const uint4*)(wB + (size_t)kt * 1024);
            const int kc = kt * 8 + acol;
            #pragma unroll
            for (int mt = 0; mt < 2; mt++) {
                const float* ap = &s_comb[(mt * 16 + arow) * CS + kc];
                uint32_t a[4];
                a[0] = __float_as_uint(ap[0]);
                a[1] = __float_as_uint(ap[8 * CS]);
                a[2] = __float_as_uint(ap[4]);
                a[3] = __float_as_uint(ap[8 * CS + 4]);
                mma_tf32(d[mt][0], a, b.x, b.y);
                mma_tf32(d[mt][1], a, b.z, b.w);
            }
        }

        #pragma unroll
        for (int mt = 0; mt < 2; mt++) {
            #pragma unroll
            for (int nt = 0; nt < 2; nt++) {
                int R = mt * 16 + (lane >> 2);
                int C = w * 16 + nt * 8 + (lane & 3) * 2;
                int m = m0 + R;
                if (m < B) {
                    float2 o;
                    o.x = fmaxf(d[mt][nt][0], 0.f);
                    o.y = fmaxf(d[mt][nt][1], 0.f);
                    *(float2*)&out[(size_t)m * F + C] = o;
                }
                if (m + 8 < B) {
                    float2 o;
                    o.x = fmaxf(d[mt][nt][2], 0.f);
                    o.y = fmaxf(d[mt][nt][3], 0.f);
                    *(float2*)&out[(size_t)(m + 8) * F + C] = o;
                }
            }
        }
    }
}

#define FUSED_SMEM ((32 * CS + 128 + 32 * S + 32 * S) * 4)

// ---------------------------------------------------------------------------
extern "C" void kernel_launch(void* const* d_in, const int* in_sizes, int n_in,
                              void* d_out, int out_size) {
    const int*   nodes        = (const int*)d_in[0];
    const int*   neigh_idx    = (const int*)d_in[1];
    const float* self_table   = (const float*)d_in[2];
    const float* neigh_table  = (const float*)d_in[3];
    const float* center       = (const float*)d_in[4];
    const float* cluster_mask = (const float*)d_in[5];
    const float* weight       = (const float*)d_in[6];
    const float* alpha        = (const float*)d_in[7];
    float* out = (float*)d_out;

    int B = in_sizes[0];
    int N = in_sizes[3] / F;

    cudaFuncSetAttribute(precompute_kernel,
                         cudaFuncAttributeMaxDynamicSharedMemorySize, A_SMEM);
    cudaFuncSetAttribute(fused_kernel,
                         cudaFuncAttributeMaxDynamicSharedMemorySize, FUSED_SMEM);

    encode_consts<<<146, 256>>>(weight, center, cluster_mask);
    precompute_kernel<<<(N + 127) / 128, 256, A_SMEM>>>(neigh_table, alpha, N);
    fused_kernel<<<(B + 31) / 32, 256, FUSED_SMEM>>>(nodes, neigh_idx,
                                                     self_table, alpha, out, B);
}

// round 14
// speedup vs baseline: 1.1497x; 1.1497x over previous
#include <cuda_runtime.h>
#include <cuda_fp16.h>
#include <math.h>
#include <stdint.h>

#define F   128
#define S   10
#define KC  16
#define MAXN 200000
#define MAXB 20000

typedef unsigned long long ull;

// static scratch (allocation-free rule)
__device__ __half   g_preh[(size_t)MAXN * F]; // t_j * (q_j @ mask), fp16
__device__ float    g_ln[MAXN];               // t_j . a_neigh
__device__ uint32_t g_wB[32 * 8 * 32 * 4];    // weight tf32 B-frags (out GEMM)
__device__ uint32_t g_cB[16 * 32 * 4];        // center tf32 B-frags (cross)
__device__ uint32_t g_mB[16 * 32 * 4];        // mask tf32 B-frags (maskMM)
__device__ float    g_c2[16];                 // |center_k|^2

// ---- packed f32x2 helpers ----
__device__ __forceinline__ ull ffma2(ull a, ull b, ull c) {
    ull d; asm("fma.rn.f32x2 %0,%1,%2,%3;" : "=l"(d) : "l"(a), "l"(b), "l"(c)); return d;
}
__device__ __forceinline__ float2 funpack(ull a) {
    float2 f; asm("mov.b64 {%0,%1},%2;" : "=f"(f.x), "=f"(f.y) : "l"(a)); return f;
}
__device__ __forceinline__ float fsum2(ull a) { float2 f = funpack(a); return f.x + f.y; }

__device__ __forceinline__ uint32_t tf32cvt(float x) {
    uint32_t u; asm("cvt.rna.tf32.f32 %0,%1;" : "=r"(u) : "f"(x)); return u;
}
__device__ __forceinline__ void mma_tf32(float* d, const uint32_t* a,
                                         uint32_t b0, uint32_t b1) {
    asm("mma.sync.aligned.m16n8k8.row.col.f32.tf32.tf32.f32 "
        "{%0,%1,%2,%3},{%4,%5,%6,%7},{%8,%9},{%0,%1,%2,%3};"
        : "+f"(d[0]), "+f"(d[1]), "+f"(d[2]), "+f"(d[3])
        : "r"(a[0]), "r"(a[1]), "r"(a[2]), "r"(a[3]), "r"(b0), "r"(b1));
}

// ---------------------------------------------------------------------------
// Kernel E: encode all constants (verified R11; warp-parallel c2).
// ---------------------------------------------------------------------------
__global__ void encode_consts(const float* __restrict__ weight,
                              const float* __restrict__ center,
                              const float* __restrict__ cluster_mask) {
    int idx = blockIdx.x * 256 + threadIdx.x;
    if (idx < 32768) {                      // weight B-frags
        int sub = idx & 3, lane = (idx >> 2) & 31;
        int ntp = (idx >> 7) & 7, kt = idx >> 10;
        int n = ntp * 16 + (sub >> 1) * 8 + (lane >> 2);
        int k = kt * 8 + (lane & 3) + (sub & 1) * 4;
        g_wB[idx] = tf32cvt(weight[n * 256 + k]);
    } else if (idx < 34816) {               // center B-frags: b = C[n][k]
        int j = idx - 32768;
        int sub = j & 3, lane = (j >> 2) & 31, kt = j >> 7;
        int n = (sub >> 1) * 8 + (lane >> 2);
        int k = kt * 8 + (lane & 3) + (sub & 1) * 4;
        g_cB[j] = tf32cvt(center[n * F + k]);
    } else if (idx < 36864) {               // mask B-frags: b = mask[k][n]
        int j = idx - 34816;
        int sub = j & 3, lane = (j >> 2) & 31, nt = j >> 7;
        int n = nt * 8 + (lane >> 2);
        int k = (sub >> 1) * 8 + (lane & 3) + (sub & 1) * 4;
        g_mB[j] = tf32cvt(cluster_mask[k * F + n]);
    } else if (idx < 37376) {               // c2: one warp per k
        int j = idx - 36864;
        int k = j >> 5, lane = j & 31;
        float4 c = *(const float4*)&center[k * F + lane * 4];
        float a = c.x * c.x + c.y * c.y + c.z * c.z + c.w * c.w;
        a += __shfl_xor_sync(0xffffffffu, a, 16);
        a += __shfl_xor_sync(0xffffffffu, a, 8);
        a += __shfl_xor_sync(0xffffffffu, a, 4);
        a += __shfl_xor_sync(0xffffffffu, a, 2);
        a += __shfl_xor_sync(0xffffffffu, a, 1);
        if (lane == 0) g_c2[k] = a;
    }
}

// ---------------------------------------------------------------------------
// Kernel A: precompute via tensor cores (verified R8/R10), fp16 output.
// ---------------------------------------------------------------------------
#define PTS 132

__global__ void __launch_bounds__(256, 3)
precompute_kernel(const float* __restrict__ neigh_table,
                  const float* __restrict__ alpha,
                  int N) {
    extern __shared__ float sm[];
    float* s_T  = sm;                       // [128][PTS]
    float* s_an = sm + 128 * PTS;           // [128]
    float* s_n2 = s_an + 128;               // [128]
    float* s_c2 = s_n2 + 128;               // [16]

    const int tid = threadIdx.x;
    const int rowbase = blockIdx.x * 128;

    if (tid < 32) ((float4*)s_an)[tid] = ((const float4*)alpha)[32 + tid];  // a_neigh
    if (tid < 16) s_c2[tid] = g_c2[tid];

    #pragma unroll
    for (int it = 0; it < 16; it++) {       // coalesced tile load
        int e = it * 256 + tid;
        int r = e >> 5, c4 = e & 31;
        int grow = min(rowbase + r, N - 1);
        float4 v = *(const float4*)&neigh_table[(size_t)grow * F + c4 * 4];
        *(float4*)&s_T[r * PTS + c4 * 4] = v;
    }
    __syncthreads();

    // ---- n2 / ln (fp32): thread = (row tid>>1, half tid&1) ----
    {
        const int r = tid >> 1, h = tid & 1;
        const float* xb = &s_T[r * PTS + h * 64];
        const float* ab = &s_an[h * 64];
        ull n2 = 0ull, ln = 0ull;
        #pragma unroll 4
        for (int ch = 0; ch < 16; ch++) {
            ulonglong2 x = *(const ulonglong2*)&xb[ch * 4];
            ulonglong2 a = *(const ulonglong2*)&ab[ch * 4];
            n2 = ffma2(x.x, x.x, n2);  n2 = ffma2(x.y, x.y, n2);
            ln = ffma2(x.x, a.x, ln);  ln = ffma2(x.y, a.y, ln);
        }
        float n2f = fsum2(n2), lnf = fsum2(ln);
        n2f += __shfl_xor_sync(0xffffffffu, n2f, 1);
        lnf += __shfl_xor_sync(0xffffffffu, lnf, 1);
        if (h == 0) {
            s_n2[r] = n2f;
            g_ln[min(rowbase + r, N - 1)] = lnf;
        }
    }

    const int l = tid & 31, w = tid >> 5;
    const int r0 = w * 16 + (l >> 2);       // lane row (and r0+8)
    const int c  = l & 3;

    // ---- cross = T @ C^T via MMA: 16 kt, N=16 (2 n-tiles) ----
    float d[2][4];
    #pragma unroll
    for (int nt = 0; nt < 2; nt++)
        #pragma unroll
        for (int i = 0; i < 4; i++) d[nt][i] = 0.f;

    #pragma unroll 4
    for (int kt = 0; kt < 16; kt++) {
        uint4 bc = *(const uint4*)&g_cB[(kt * 32 + l) * 4];
        const float* ap = &s_T[r0 * PTS + kt * 8 + c];
        uint32_t a[4];
        a[0] = tf32cvt(ap[0]);
        a[1] = tf32cvt(ap[8 * PTS]);
        a[2] = tf32cvt(ap[4]);
        a[3] = tf32cvt(ap[8 * PTS + 4]);
        mma_tf32(d[0], a, bc.x, bc.y);
        mma_tf32(d[1], a, bc.z, bc.w);
    }
    __syncthreads();                        // s_n2 ready

    // ---- q epilogue in registers ----
    float qv[2][4];
    {
        const float n2A = s_n2[r0], n2B = s_n2[r0 + 8];
        #pragma unroll
        for (int nt = 0; nt < 2; nt++) {
            int k0 = nt * 8 + 2 * c;
            float c2a = s_c2[k0] + 1.f, c2b = s_c2[k0 + 1] + 1.f;
            qv[nt][0] = 1.f / (n2A - 2.f * d[nt][0] + c2a);
            qv[nt][1] = 1.f / (n2A - 2.f * d[nt][1] + c2b);
            qv[nt][2] = 1.f / (n2B - 2.f * d[nt][2] + c2a);
            qv[nt][3] = 1.f / (n2B - 2.f * d[nt][3] + c2b);
        }
    }

    // ---- intra-warp redistribution to maskMM A-frag layout (shfl) ----
    uint32_t aq[2][4];
    {
        const unsigned FULLM = 0xffffffffu;
        const int ls1 = (l & ~3) | (c >> 1);
        const int ls2 = ls1 + 2;
        const bool odd = (c & 1) != 0;
        #pragma unroll
        for (int kt = 0; kt < 2; kt++) {
            float a0 = __shfl_sync(FULLM, qv[kt][0], ls1);
            float a1 = __shfl_sync(FULLM, qv[kt][1], ls1);
            float b0 = __shfl_sync(FULLM, qv[kt][2], ls1);
            float b1 = __shfl_sync(FULLM, qv[kt][3], ls1);
            float e0 = __shfl_sync(FULLM, qv[kt][0], ls2);
            float e1 = __shfl_sync(FULLM, qv[kt][1], ls2);
            float f0 = __shfl_sync(FULLM, qv[kt][2], ls2);
            float f1 = __shfl_sync(FULLM, qv[kt][3], ls2);
            aq[kt][0] = tf32cvt(odd ? a1 : a0);
            aq[kt][1] = tf32cvt(odd ? b1 : b0);
            aq[kt][2] = tf32cvt(odd ? e1 : e0);
            aq[kt][3] = tf32cvt(odd ? f1 : f0);
        }
    }

    const int growA = min(rowbase + r0, N - 1);
    const int growB = min(rowbase + r0 + 8, N - 1);
    __half* opA = g_preh + (size_t)growA * F;
    __half* opB = g_preh + (size_t)growB * F;

    // ---- m = q @ mask via MMA; pre = T * m; store fp16 ----
    #pragma unroll 4
    for (int nt = 0; nt < 16; nt++) {
        uint4 bm = *(const uint4*)&g_mB[(nt * 32 + l) * 4];
        float dm[4] = {0.f, 0.f, 0.f, 0.f};
        mma_tf32(dm, aq[0], bm.x, bm.y);
        mma_tf32(dm, aq[1], bm.z, bm.w);

        int col = nt * 8 + 2 * c;
        float2 tA = *(const float2*)&s_T[r0 * PTS + col];
        float2 tB = *(const float2*)&s_T[(r0 + 8) * PTS + col];
        *(__half2*)&opA[col] = __floats2half2_rn(tA.x * dm[0], tA.y * dm[1]);
        *(__half2*)&opB[col] = __floats2half2_rn(tB.x * dm[2], tB.y * dm[3]);
    }
}

#define A_SMEM ((128 * PTS + 128 + 128 + 16) * 4)

// ---------------------------------------------------------------------------
// Kernel B: fused gather + attention + TF32 MMA GEMM (R10 structure, fp16
// gather). grid=ceil(B/32), blk=256.
// ---------------------------------------------------------------------------
#define CS 268

__global__ void __launch_bounds__(256, 3)
fused_kernel(const int* __restrict__ nodes,
             const int* __restrict__ neigh_idx,
             const float* __restrict__ self_table,
             const float* __restrict__ alpha,
             float* __restrict__ out, int B) {
    extern __shared__ float smf[];
    float* s_comb  = smf;             // [32][CS] tf32-bit floats
    float* s_alpha = smf + 32 * CS;   // [128]

    const int tid = threadIdx.x;
    if (tid < 32) ((float4*)s_alpha)[tid] = ((const float4*)alpha)[tid];  // a_self
    __syncthreads();

    const int m0 = blockIdx.x * 32;

    // ---- phase 1: gather + attention ----
    {
        const int r = tid >> 3, g = tid & 7;
        const int row = min(m0 + r, B - 1);
        const int node = nodes[row];
        const float4* sp = (const float4*)(self_table + (size_t)node * F + g * 16);
        float4 sf[4];
        float lp = 0.f;
        #pragma unroll
        for (int j = 0; j < 4; j++) {
            sf[j] = sp[j];
            float4 av = *(const float4*)&s_alpha[g * 16 + j * 4];
            lp += sf[j].x * av.x + sf[j].y * av.y + sf[j].z * av.z + sf[j].w * av.w;
        }
        lp += __shfl_xor_sync(0xffffffffu, lp, 1);
        lp += __shfl_xor_sync(0xffffffffu, lp, 2);
        lp += __shfl_xor_sync(0xffffffffu, lp, 4);

        int ji[S];
        #pragma unroll
        for (int s = 0; s < S; s++) ji[s] = neigh_idx[row * S + s];
        float att[S], asum = 0.f;
        #pragma unroll
        for (int s = 0; s < S; s++) {
            float lgt = fmaxf(lp + g_ln[ji[s]], 0.f);
            att[s] = __expf(lgt);
            asum += att[s];
        }
        const float inv = 1.f / asum;

        float2 agg[8];
        #pragma unroll
        for (int j = 0; j < 8; j++) agg[j] = make_float2(0.f, 0.f);
        #pragma unroll
        for (int s = 0; s < S; s++) {
            const float wt = att[s] * inv;
            const uint4* pp = (const uint4*)(g_preh + (size_t)ji[s] * F + g * 16);
            uint4 u0 = pp[0], u1 = pp[1];        // 16 halfs = 32B
            uint32_t uu[8] = {u0.x, u0.y, u0.z, u0.w, u1.x, u1.y, u1.z, u1.w};
            #pragma unroll
            for (int jj = 0; jj < 8; jj++) {
                float2 f = __half22float2(*(const __half2*)&uu[jj]);
                agg[jj].x += wt * f.x;
                agg[jj].y += wt * f.y;
            }
        }

        #pragma unroll
        for (int j = 0; j < 4; j++) {
            float4 a, b;
            a.x = __uint_as_float(tf32cvt(sf[j].x));
            a.y = __uint_as_float(tf32cvt(sf[j].y));
            a.z = __uint_as_float(tf32cvt(sf[j].z));
            a.w = __uint_as_float(tf32cvt(sf[j].w));
            b.x = __uint_as_float(tf32cvt(agg[j * 2].x));
            b.y = __uint_as_float(tf32cvt(agg[j * 2].y));
            b.z = __uint_as_float(tf32cvt(agg[j * 2 + 1].x));
            b.w = __uint_as_float(tf32cvt(agg[j * 2 + 1].y));
            *(float4*)&s_comb[r * CS + g * 16 + j * 4]       = a;
            *(float4*)&s_comb[r * CS + 128 + g * 16 + j * 4] = b;
        }
    }
    __syncthreads();

    // ---- phase 2: TF32 MMA (verified R7/R8) ----
    {
        const int lane = tid & 31, w = tid >> 5;
        float d[2][2][4];
        #pragma unroll
        for (int mt = 0; mt < 2; mt++)
            #pragma unroll
            for (int nt = 0; nt < 2; nt++)
                #pragma unroll
                for (int i = 0; i < 4; i++) d[mt][nt][i] = 0.f;

        const uint32_t* wB = &g_wB[((size_t)w * 32 + lane) * 4];
        const int arow = lane >> 2, acol = lane & 3;

        #pragma unroll 4
        for (int kt = 0; kt < 32; kt++) {
            uint4 b = *(const uint4*)(wB + (size_t)kt * 1024);
            const int kc = kt * 8 + acol;
            #pragma unroll
            for (int mt = 0; mt < 2; mt++) {
                const float* ap = &s_comb[(mt * 16 + arow) * CS + kc];
                uint32_t a[4];
                a[0] = __float_as_uint(ap[0]);
                a[1] = __float_as_uint(ap[8 * CS]);
                a[2] = __float_as_uint(ap[4]);
                a[3] = __float_as_uint(ap[8 * CS + 4]);
                mma_tf32(d[mt][0], a, b.x, b.y);
                mma_tf32(d[mt][1], a, b.z, b.w);
            }
        }

        #pragma unroll
        for (int mt = 0; mt < 2; mt++) {
            #pragma unroll
            for (int nt = 0; nt < 2; nt++) {
                int R = mt * 16 + (lane >> 2);
                int C = w * 16 + nt * 8 + (lane & 3) * 2;
                int m = m0 + R;
                if (m < B) {
                    float2 o;
                    o.x = fmaxf(d[mt][nt][0], 0.f);
                    o.y = fmaxf(d[mt][nt][1], 0.f);
                    *(float2*)&out[(size_t)m * F + C] = o;
                }
                if (m + 8 < B) {
                    float2 o;
                    o.x = fmaxf(d[mt][nt][2], 0.f);
                    o.y = fmaxf(d[mt][nt][3], 0.f);
                    *(float2*)&out[(size_t)(m + 8) * F + C] = o;
                }
            }
        }
    }
}

#define FUSED_SMEM ((32 * CS + 128) * 4)

// ---------------------------------------------------------------------------
extern "C" void kernel_launch(void* const* d_in, const int* in_sizes, int n_in,
                              void* d_out, int out_size) {
    const int*   nodes        = (const int*)d_in[0];
    const int*   neigh_idx    = (const int*)d_in[1];
    const float* self_table   = (const float*)d_in[2];
    const float* neigh_table  = (const float*)d_in[3];
    const float* center       = (const float*)d_in[4];
    const float* cluster_mask = (const float*)d_in[5];
    const float* weight       = (const float*)d_in[6];
    const float* alpha        = (const float*)d_in[7];
    float* out = (float*)d_out;

    int B = in_sizes[0];
    int N = in_sizes[3] / F;

    cudaFuncSetAttribute(precompute_kernel,
                         cudaFuncAttributeMaxDynamicSharedMemorySize, A_SMEM);
    cudaFuncSetAttribute(fused_kernel,
                         cudaFuncAttributeMaxDynamicSharedMemorySize, FUSED_SMEM);

    encode_consts<<<146, 256>>>(weight, center, cluster_mask);
    precompute_kernel<<<(N + 127) / 128, 256, A_SMEM>>>(neigh_table, alpha, N);
    fused_kernel<<<(B + 31) / 32, 256, FUSED_SMEM>>>(nodes, neigh_idx,
                                                     self_table, alpha, out, B);
}